// round 8
// baseline (speedup 1.0000x reference)
#include <cuda_runtime.h>
#include <cuda_bf16.h>
#include <cstdint>

// ---------------------------------------------------------------------------
// Problem constants
// ---------------------------------------------------------------------------
#define NT   20     // trees
#define NF   128    // features (K)
#define NN   31     // internal nodes (padded to 32 = GEMM N)
#define NLF  32     // leaves
#define ROWS 128    // batch rows per CTA
#define NTHR 256    // threads per CTA (8 warps, m16 slice per warp)
#define XSTRB 272   // x/W row stride bytes (136 bf16, conflict-free ldmatrix)
#define WH_STRIDE 8704   // bytes between hi and lo W planes (32*272)

// Shared memory layout (bytes)
#define SM_XHI  0
#define SM_XLO  34816
#define SM_W    69632        // [h][32][136] bf16
#define SM_STG  87040        // 8 warps x 16 x 34 floats
#define SM_BIAS 104448       // 32 floats
#define SM_LCP  104576       // 64 floats
#define SM_TOTAL 104832

// ---------------------------------------------------------------------------
// Device scratch (allocation-free)
// ---------------------------------------------------------------------------
__device__ __align__(16) __nv_bfloat16 g_W[NT][2][32][NF];  // [tree][hi/lo][node][feat]
__device__ float g_lcp[NT * NLF * 2];
__device__ float g_tw[NT];

// ---------------------------------------------------------------------------
// Helpers
// ---------------------------------------------------------------------------
__device__ __forceinline__ uint32_t smem_u32(const void* p) {
    uint32_t a;
    asm("{ .reg .u64 t; cvta.to.shared.u64 t, %1; cvt.u32.u64 %0, t; }" : "=r"(a) : "l"(p));
    return a;
}

__device__ __forceinline__ void ldsm4(uint32_t* r, uint32_t addr) {
    asm volatile("ldmatrix.sync.aligned.m8n8.x4.shared.b16 {%0,%1,%2,%3}, [%4];"
                 : "=r"(r[0]), "=r"(r[1]), "=r"(r[2]), "=r"(r[3]) : "r"(addr));
}

__device__ __forceinline__ void mma_bf16(float* c, const uint32_t* a, const uint32_t* b) {
    asm volatile("mma.sync.aligned.m16n8k16.row.col.f32.bf16.bf16.f32 "
                 "{%0,%1,%2,%3}, {%4,%5,%6,%7}, {%8,%9}, {%0,%1,%2,%3};"
                 : "+f"(c[0]), "+f"(c[1]), "+f"(c[2]), "+f"(c[3])
                 : "r"(a[0]), "r"(a[1]), "r"(a[2]), "r"(a[3]), "r"(b[0]), "r"(b[1]));
}

__device__ __forceinline__ float fast_tanh(float x) {
    float r; asm("tanh.approx.f32 %0, %1;" : "=f"(r) : "f"(x)); return r;
}

__device__ __forceinline__ uint32_t pack_bf2(__nv_bfloat16 a, __nv_bfloat16 b) {
    __nv_bfloat162 t(a, b);
    return *reinterpret_cast<uint32_t*>(&t);
}

// ---------------------------------------------------------------------------
// Prep kernel: bf16 hi/lo masked weights, leaf softmax, tree softmax
// ---------------------------------------------------------------------------
__global__ void prep_kernel(const float* __restrict__ sw,
                            const float* __restrict__ ll,
                            const float* __restrict__ tw,
                            const float* __restrict__ fm)
{
    int idx = blockIdx.x * blockDim.x + threadIdx.x;
    const int total = NT * 32 * NF;
    if (idx < total) {
        int t = idx / (32 * NF);
        int r = (idx / NF) & 31;
        int f = idx & (NF - 1);
        float v = 0.0f;
        if (r < NN) v = sw[(t * NN + r) * NF + f] * fm[t * NF + f];
        __nv_bfloat16 hi = __float2bfloat16(v);
        float rem = v - __bfloat162float(hi);
        g_W[t][0][r][f] = hi;
        g_W[t][1][r][f] = __float2bfloat16(rem);
    }
    if (idx < NT * NLF) {
        float a = ll[2 * idx], b = ll[2 * idx + 1];
        float m  = fmaxf(a, b);
        float e0 = expf(a - m), e1 = expf(b - m);
        float inv = 1.0f / (e0 + e1);
        g_lcp[2 * idx]     = e0 * inv;
        g_lcp[2 * idx + 1] = e1 * inv;
    }
    if (idx == 0) {
        float m = tw[0];
        for (int t = 1; t < NT; ++t) m = fmaxf(m, tw[t]);
        float e[NT]; float s = 0.0f;
        for (int t = 0; t < NT; ++t) { e[t] = expf(tw[t] - m); s += e[t]; }
        float inv = 1.0f / s;
        for (int t = 0; t < NT; ++t) g_tw[t] = e[t] * inv;
    }
}

// ---------------------------------------------------------------------------
// Main fused HMMA kernel: 8 warps, m16 per warp, 3 independent acc chains
// ---------------------------------------------------------------------------
__global__ __launch_bounds__(NTHR, 2) void forest_mma(
    const float* __restrict__ x,
    const float* __restrict__ sbias,
    float* __restrict__ out)
{
    extern __shared__ __align__(16) uint8_t smem[];
    const uint32_t sbase = smem_u32(smem);

    const int tid  = threadIdx.x;
    const int wid  = tid >> 5;
    const int lane = tid & 31;
    const int grp  = lane >> 3;
    const int sub  = lane & 7;

    float* stage = reinterpret_cast<float*>(smem + SM_STG) + wid * 16 * 34;
    float* sBias = reinterpret_cast<float*>(smem + SM_BIAS);
    float* sLcp  = reinterpret_cast<float*>(smem + SM_LCP);

    // ---- Load x tile, convert to bf16 hi/lo, store padded ----
    {
        const float4* x4 = reinterpret_cast<const float4*>(
            x + (size_t)blockIdx.x * ROWS * NF);
        #pragma unroll
        for (int i = 0; i < 16; ++i) {            // 4096 float4 / 256 threads
            int lin = tid + i * NTHR;
            int r  = lin >> 5;
            int c4 = lin & 31;
            float4 v = x4[lin];
            __nv_bfloat16 hx = __float2bfloat16(v.x);
            __nv_bfloat16 hy = __float2bfloat16(v.y);
            __nv_bfloat16 hz = __float2bfloat16(v.z);
            __nv_bfloat16 hw = __float2bfloat16(v.w);
            uint32_t* dh = reinterpret_cast<uint32_t*>(smem + SM_XHI + r * XSTRB + c4 * 8);
            uint32_t* dl = reinterpret_cast<uint32_t*>(smem + SM_XLO + r * XSTRB + c4 * 8);
            dh[0] = pack_bf2(hx, hy);
            dh[1] = pack_bf2(hz, hw);
            dl[0] = pack_bf2(__float2bfloat16(v.x - __bfloat162float(hx)),
                             __float2bfloat16(v.y - __bfloat162float(hy)));
            dl[1] = pack_bf2(__float2bfloat16(v.z - __bfloat162float(hz)),
                             __float2bfloat16(v.w - __bfloat162float(hw)));
        }
    }

    // ---- Load tree 0's W/bias/lcp into smem ----
    {
        const float4* src = reinterpret_cast<const float4*>(&g_W[0][0][0][0]);
        #pragma unroll
        for (int j = 0; j < 4; ++j) {             // 1024 float4 / 256 threads
            int idx = tid + j * NTHR;
            int h   = idx >> 9;
            int rem = idx & 511;
            int n   = rem >> 4;
            int k8  = rem & 15;
            float4 v = src[idx];
            *reinterpret_cast<float4*>(smem + SM_W + h * WH_STRIDE + n * XSTRB + k8 * 16) = v;
        }
        if (tid < NN)      sBias[tid] = sbias[tid];
        if (tid < NLF * 2) sLcp[tid]  = g_lcp[tid] * g_tw[0];
    }
    __syncthreads();

    // ---- Per-lane ldmatrix base addresses ----
    // A (m16k16): matrices (m0k0),(m8k0),(m0k8),(m8k8)
    const int aRow  = ((grp & 1) << 3) + sub;
    const int aCol  = (grp >> 1) << 4;            // bytes
    const int warpM = wid << 4;                   // 16 rows per warp
    const uint32_t aHi = sbase + SM_XHI + (warpM + aRow) * XSTRB + aCol;
    const uint32_t aLo = aHi + (SM_XLO - SM_XHI);
    // B (n16k16 per ldsm4): matrices (n0k0),(n0k8),(n8k0),(n8k8)
    const int bRow = ((grp >> 1) << 3) + sub;
    const int bCol = (grp & 1) << 4;              // bytes
    const uint32_t bHi0 = sbase + SM_W + (bRow)      * XSTRB + bCol;   // n-tiles 0,1
    const uint32_t bHi1 = sbase + SM_W + (bRow + 16) * XSTRB + bCol;   // n-tiles 2,3
    const uint32_t bLo0 = bHi0 + WH_STRIDE;
    const uint32_t bLo1 = bHi1 + WH_STRIDE;

    float o0 = 0.0f, o1 = 0.0f;

    for (int t = 0; t < NT; ++t) {
        // -- Prefetch next tree into registers (overlaps K loop) --
        float4 pw[4];
        float  pb = 0.0f, pl = 0.0f;
        if (t + 1 < NT) {
            const float4* src = reinterpret_cast<const float4*>(&g_W[t + 1][0][0][0]);
            #pragma unroll
            for (int j = 0; j < 4; ++j) pw[j] = src[tid + j * NTHR];
            if (tid < NN)      pb = sbias[(t + 1) * NN + tid];
            if (tid < NLF * 2) pl = g_lcp[(t + 1) * NLF * 2 + tid] * g_tw[t + 1];
        }

        // -- K loop: 8 k16 steps; 3 SEPARATE accumulator sets (independent
        //    HMMA dep-chains: hh, hl, lh -> 12 concurrent streams) --
        float accH[4][4], accM[4][4], accL[4][4];
        #pragma unroll
        for (int n = 0; n < 4; ++n)
            #pragma unroll
            for (int i = 0; i < 4; ++i) { accH[n][i] = 0.f; accM[n][i] = 0.f; accL[n][i] = 0.f; }

        #pragma unroll
        for (int k = 0; k < 8; ++k) {
            const uint32_t ko = k * 32;
            uint32_t ah[4], al[4], bh0[4], bh1[4], bl0[4], bl1[4];
            ldsm4(ah,  aHi  + ko); ldsm4(al,  aLo  + ko);
            ldsm4(bh0, bHi0 + ko); ldsm4(bh1, bHi1 + ko);
            ldsm4(bl0, bLo0 + ko); ldsm4(bl1, bLo1 + ko);

            mma_bf16(accH[0], ah, bh0);   mma_bf16(accH[1], ah, bh0 + 2);
            mma_bf16(accH[2], ah, bh1);   mma_bf16(accH[3], ah, bh1 + 2);
            mma_bf16(accM[0], ah, bl0);   mma_bf16(accM[1], ah, bl0 + 2);
            mma_bf16(accM[2], ah, bl1);   mma_bf16(accM[3], ah, bl1 + 2);
            mma_bf16(accL[0], al, bh0);   mma_bf16(accL[1], al, bh0 + 2);
            mma_bf16(accL[2], al, bh1);   mma_bf16(accL[3], al, bh1 + 2);
        }

        // -- Combine terms and transpose through per-warp staging buffer --
        {
            const int r0 = lane >> 2;
            const int cb = (lane & 3) << 1;
            #pragma unroll
            for (int n = 0; n < 4; ++n) {
                const int col = n * 8 + cb;
                float v0 = accH[n][0] + accM[n][0] + accL[n][0];
                float v1 = accH[n][1] + accM[n][1] + accL[n][1];
                float v2 = accH[n][2] + accM[n][2] + accL[n][2];
                float v3 = accH[n][3] + accM[n][3] + accL[n][3];
                *reinterpret_cast<float2*>(&stage[(r0)     * 34 + col]) = make_float2(v0, v1);
                *reinterpret_cast<float2*>(&stage[(r0 + 8) * 34 + col]) = make_float2(v2, v3);
            }
        }
        __syncwarp();

        // -- Epilogue: lanes 0-15 each own one full row --
        if (lane < 16) {
            float g[NN];
            const float* row = &stage[lane * 34];
            #pragma unroll
            for (int n = 0; n < NN; ++n) {
                float lg = row[n] + sBias[n];
                g[n] = fmaf(fast_tanh(0.5f * lg), 0.5f, 0.5f);   // sigmoid
            }
            float P[NLF];
            P[0] = 1.0f;
            #pragma unroll
            for (int lvl = 0; lvl < 5; ++lvl) {
                const int base = (1 << lvl) - 1;
                const int cnt  = 1 << lvl;
                #pragma unroll
                for (int j = cnt - 1; j >= 0; --j) {
                    float gg = g[base + j];
                    float pj = P[j];
                    P[2 * j + 1] = pj * gg;
                    P[2 * j]     = fmaf(-pj, gg, pj);
                }
            }
            float t0 = 0.0f, t1 = 0.0f;
            #pragma unroll
            for (int l = 0; l < NLF; ++l) {
                t0 = fmaf(P[l], sLcp[2 * l],     t0);
                t1 = fmaf(P[l], sLcp[2 * l + 1], t1);
            }
            o0 += t0; o1 += t1;
        }
        __syncwarp();   // stage reuse next tree

        // -- Swap in prefetched tree (W single-buffered: full barrier) --
        if (t + 1 < NT) {
            __syncthreads();
            #pragma unroll
            for (int j = 0; j < 4; ++j) {
                int idx = tid + j * NTHR;
                int h   = idx >> 9;
                int rem = idx & 511;
                int n   = rem >> 4;
                int k8  = rem & 15;
                *reinterpret_cast<float4*>(smem + SM_W + h * WH_STRIDE + n * XSTRB + k8 * 16) = pw[j];
            }
            if (tid < NN)      sBias[tid] = pb;
            if (tid < NLF * 2) sLcp[tid]  = pl;
            __syncthreads();
        }
    }

    // warp w, lane l (<16) owns global row blockIdx*128 + w*16 + lane
    if (lane < 16) {
        const size_t orow = (size_t)blockIdx.x * ROWS + warpM + lane;
        reinterpret_cast<float2*>(out)[orow] = make_float2(o0, o1);
    }
}

// ---------------------------------------------------------------------------
// Launch
// ---------------------------------------------------------------------------
extern "C" void kernel_launch(void* const* d_in, const int* in_sizes, int n_in,
                              void* d_out, int out_size)
{
    const float* x  = (const float*)d_in[0];   // (B, 128)
    const float* sw = (const float*)d_in[1];   // (20, 31, 128)
    const float* sb = (const float*)d_in[2];   // (20, 31)
    const float* ll = (const float*)d_in[3];   // (20, 32, 2)
    const float* tw = (const float*)d_in[4];   // (20,)
    const float* fm = (const float*)d_in[5];   // (20, 128)
    float* out = (float*)d_out;                // (B, 2)

    const int B = in_sizes[0] / NF;

    cudaFuncSetAttribute(forest_mma,
                         cudaFuncAttributeMaxDynamicSharedMemorySize, SM_TOTAL);

    const int prep_total = NT * 32 * NF;
    prep_kernel<<<(prep_total + 255) / 256, 256>>>(sw, ll, tw, fm);
    forest_mma<<<B / ROWS, NTHR, SM_TOTAL>>>(x, sb, out);
}

// round 12
// speedup vs baseline: 1.4353x; 1.4353x over previous
#include <cuda_runtime.h>
#include <cuda_bf16.h>
#include <cstdint>

// ---------------------------------------------------------------------------
// Problem constants
// ---------------------------------------------------------------------------
#define NT   20     // trees
#define NF   128    // features (K)
#define NN   31     // internal nodes (padded to 32 = GEMM N)
#define NLF  32     // leaves
#define ROWS 128    // batch rows per CTA
#define NTHR 128    // 4 warps, m32 per warp
#define XSTRB 272   // row stride bytes (136 bf16, conflict-free ldmatrix)
#define WH_STRIDE 8704    // bytes between hi and lo W planes (32*272)
#define WBUF_STRIDE 17408 // bytes per W double-buffer slot

// Shared memory layout (bytes)
#define SM_XLO  0         // persistent A-lo (34816)
#define SM_XHI  34816     // x-hi during init ONLY; recycled as W double buffer
#define SM_W    34816     // W buffers: [2][2 planes][32][272B]
#define SM_STG  69632     // 4 warps x 32 x 34 floats (17408)
#define SM_BIAS 87040     // 2 x 32 floats (double-buffered consts)
#define SM_LCP  87296     // 2 x 64 floats
#define SM_TOTAL 87808

// ---------------------------------------------------------------------------
// Device scratch (allocation-free)
// ---------------------------------------------------------------------------
__device__ __align__(16) __nv_bfloat16 g_W[NT][2][32][NF];  // [tree][hi/lo][node][feat]
__device__ float g_lcp[NT * NLF * 2];
__device__ float g_tw[NT];

// ---------------------------------------------------------------------------
// Helpers
// ---------------------------------------------------------------------------
__device__ __forceinline__ uint32_t smem_u32(const void* p) {
    uint32_t a;
    asm("{ .reg .u64 t; cvta.to.shared.u64 t, %1; cvt.u32.u64 %0, t; }" : "=r"(a) : "l"(p));
    return a;
}

__device__ __forceinline__ void ldsm4(uint32_t* r, uint32_t addr) {
    asm volatile("ldmatrix.sync.aligned.m8n8.x4.shared.b16 {%0,%1,%2,%3}, [%4];"
                 : "=r"(r[0]), "=r"(r[1]), "=r"(r[2]), "=r"(r[3]) : "r"(addr));
}

__device__ __forceinline__ void mma_bf16(float* c, const uint32_t* a, const uint32_t* b) {
    asm volatile("mma.sync.aligned.m16n8k16.row.col.f32.bf16.bf16.f32 "
                 "{%0,%1,%2,%3}, {%4,%5,%6,%7}, {%8,%9}, {%0,%1,%2,%3};"
                 : "+f"(c[0]), "+f"(c[1]), "+f"(c[2]), "+f"(c[3])
                 : "r"(a[0]), "r"(a[1]), "r"(a[2]), "r"(a[3]), "r"(b[0]), "r"(b[1]));
}

__device__ __forceinline__ void cp_async16(uint32_t smem_dst, const void* gptr) {
    asm volatile("cp.async.cg.shared.global [%0], [%1], 16;"
                 :: "r"(smem_dst), "l"(gptr) : "memory");
}
__device__ __forceinline__ void cp_commit() {
    asm volatile("cp.async.commit_group;" ::: "memory");
}
__device__ __forceinline__ void cp_wait1() {
    asm volatile("cp.async.wait_group 1;" ::: "memory");
}

__device__ __forceinline__ float fast_tanh(float x) {
    float r; asm("tanh.approx.f32 %0, %1;" : "=f"(r) : "f"(x)); return r;
}

__device__ __forceinline__ uint32_t pack_bf2(__nv_bfloat16 a, __nv_bfloat16 b) {
    __nv_bfloat162 t(a, b);
    return *reinterpret_cast<uint32_t*>(&t);
}

// ---------------------------------------------------------------------------
// Prep kernel: bf16 hi/lo masked weights, leaf softmax, tree softmax
// ---------------------------------------------------------------------------
__global__ void prep_kernel(const float* __restrict__ sw,
                            const float* __restrict__ ll,
                            const float* __restrict__ tw,
                            const float* __restrict__ fm)
{
    int idx = blockIdx.x * blockDim.x + threadIdx.x;
    const int total = NT * 32 * NF;
    if (idx < total) {
        int t = idx / (32 * NF);
        int r = (idx / NF) & 31;
        int f = idx & (NF - 1);
        float v = 0.0f;
        if (r < NN) v = sw[(t * NN + r) * NF + f] * fm[t * NF + f];
        __nv_bfloat16 hi = __float2bfloat16(v);
        float rem = v - __bfloat162float(hi);
        g_W[t][0][r][f] = hi;
        g_W[t][1][r][f] = __float2bfloat16(rem);
    }
    if (idx < NT * NLF) {
        float a = ll[2 * idx], b = ll[2 * idx + 1];
        float m  = fmaxf(a, b);
        float e0 = expf(a - m), e1 = expf(b - m);
        float inv = 1.0f / (e0 + e1);
        g_lcp[2 * idx]     = e0 * inv;
        g_lcp[2 * idx + 1] = e1 * inv;
    }
    if (idx == 0) {
        float m = tw[0];
        for (int t = 1; t < NT; ++t) m = fmaxf(m, tw[t]);
        float e[NT]; float s = 0.0f;
        for (int t = 0; t < NT; ++t) { e[t] = expf(tw[t] - m); s += e[t]; }
        float inv = 1.0f / s;
        for (int t = 0; t < NT; ++t) g_tw[t] = e[t] * inv;
    }
}

// ---------------------------------------------------------------------------
// Main fused HMMA kernel: A-hi persistent in registers, A-lo in smem,
// W double-buffered via cp.async. 4 warps x m32.
// ---------------------------------------------------------------------------
__global__ __launch_bounds__(NTHR, 2) void forest_mma(
    const float* __restrict__ x,
    const float* __restrict__ sbias,
    float* __restrict__ out)
{
    extern __shared__ __align__(16) uint8_t smem[];
    const uint32_t sbase = smem_u32(smem);

    const int tid  = threadIdx.x;
    const int wid  = tid >> 5;
    const int lane = tid & 31;
    const int grp  = lane >> 3;
    const int sub  = lane & 7;

    float* stage = reinterpret_cast<float*>(smem + SM_STG) + wid * 32 * 34;
    float* sBias = reinterpret_cast<float*>(smem + SM_BIAS);   // [2][32]
    float* sLcp  = reinterpret_cast<float*>(smem + SM_LCP);    // [2][64]

    // ---- Init: load x tile, bf16 hi/lo, to XHI (temp) / XLO (persistent) ----
    {
        const float4* x4 = reinterpret_cast<const float4*>(
            x + (size_t)blockIdx.x * ROWS * NF);
        #pragma unroll
        for (int i = 0; i < 32; ++i) {            // 4096 float4 / 128 threads
            int lin = tid + i * NTHR;
            int r  = lin >> 5;
            int c4 = lin & 31;
            float4 v = x4[lin];
            __nv_bfloat16 hx = __float2bfloat16(v.x);
            __nv_bfloat16 hy = __float2bfloat16(v.y);
            __nv_bfloat16 hz = __float2bfloat16(v.z);
            __nv_bfloat16 hw = __float2bfloat16(v.w);
            uint32_t* dh = reinterpret_cast<uint32_t*>(smem + SM_XHI + r * XSTRB + c4 * 8);
            uint32_t* dl = reinterpret_cast<uint32_t*>(smem + SM_XLO + r * XSTRB + c4 * 8);
            dh[0] = pack_bf2(hx, hy);
            dh[1] = pack_bf2(hz, hw);
            dl[0] = pack_bf2(__float2bfloat16(v.x - __bfloat162float(hx)),
                             __float2bfloat16(v.y - __bfloat162float(hy)));
            dl[1] = pack_bf2(__float2bfloat16(v.z - __bfloat162float(hz)),
                             __float2bfloat16(v.w - __bfloat162float(hw)));
        }
    }
    __syncthreads();

    // ---- Per-lane ldmatrix addressing ----
    const int aRow  = ((grp & 1) << 3) + sub;
    const int aCol  = (grp >> 1) << 4;            // bytes
    const int warpM = wid << 5;                   // 32 rows per warp
    const uint32_t aHi = sbase + SM_XHI + (warpM + aRow) * XSTRB + aCol;
    const uint32_t aLo = sbase + SM_XLO + (warpM + aRow) * XSTRB + aCol;
    const int bRow = ((grp >> 1) << 3) + sub;
    const int bCol = (grp & 1) << 4;              // bytes

    // ---- Hoist A-hi fragments into persistent registers (64 regs) ----
    uint32_t ahK[8][2][4];
    #pragma unroll
    for (int k = 0; k < 8; ++k) {
        ldsm4(ahK[k][0], aHi + k * 32);
        ldsm4(ahK[k][1], aHi + 16 * XSTRB + k * 32);
    }

    // ---- Consts for trees 0,1 ----
    if (tid < NN)      { sBias[tid]      = sbias[tid];
                         sBias[32 + tid] = sbias[NN + tid]; }
    if (tid < NLF * 2) { sLcp[tid]       = g_lcp[tid] * g_tw[0];
                         sLcp[64 + tid]  = g_lcp[NLF * 2 + tid] * g_tw[1]; }

    // All warps must finish reading XHI before cp.async overwrites it
    __syncthreads();

    // ---- Issue W(0), W(1) via cp.async (1024 x 16B chunks each) ----
    #pragma unroll
    for (int b = 0; b < 2; ++b) {
        const uint8_t* src = reinterpret_cast<const uint8_t*>(&g_W[b][0][0][0]);
        const uint32_t wb  = sbase + SM_W + b * WBUF_STRIDE;
        #pragma unroll
        for (int j = 0; j < 8; ++j) {
            int idx = tid + j * NTHR;          // 0..1023
            int h   = idx >> 9;
            int rem = idx & 511;
            int n   = rem >> 4;
            int k8  = rem & 15;
            cp_async16(wb + h * WH_STRIDE + n * XSTRB + k8 * 16, src + idx * 16);
        }
        cp_commit();
    }

    float o0 = 0.0f, o1 = 0.0f;

    for (int t = 0; t < NT; ++t) {
        const int cur = t & 1;
        cp_wait1();          // W(t) landed (W(t+1) may still fly)
        __syncthreads();     // make W(t)/consts(t) visible to all warps

        const uint32_t wb  = sbase + SM_W + cur * WBUF_STRIDE;
        const uint32_t bHi0 = wb + bRow * XSTRB + bCol;
        const uint32_t bHi1 = bHi0 + 16 * XSTRB;
        const uint32_t bLo0 = bHi0 + WH_STRIDE;
        const uint32_t bLo1 = bHi1 + WH_STRIDE;

        // -- K loop: 6 ldsm4 + 24 MMA per k-step; 2 acc sets (16 indep chains) --
        float accH[2][4][4], accC[2][4][4];
        #pragma unroll
        for (int m = 0; m < 2; ++m)
            #pragma unroll
            for (int n = 0; n < 4; ++n)
                #pragma unroll
                for (int i = 0; i < 4; ++i) { accH[m][n][i] = 0.f; accC[m][n][i] = 0.f; }

        #pragma unroll
        for (int k = 0; k < 8; ++k) {
            const uint32_t ko = k * 32;
            uint32_t al0[4], al1[4], bh0[4], bh1[4], bl0[4], bl1[4];
            ldsm4(al0, aLo + ko);
            ldsm4(al1, aLo + 16 * XSTRB + ko);
            ldsm4(bh0, bHi0 + ko); ldsm4(bh1, bHi1 + ko);
            ldsm4(bl0, bLo0 + ko); ldsm4(bl1, bLo1 + ko);

            // main: A-hi * B-hi
            mma_bf16(accH[0][0], ahK[k][0], bh0);  mma_bf16(accH[0][1], ahK[k][0], bh0 + 2);
            mma_bf16(accH[0][2], ahK[k][0], bh1);  mma_bf16(accH[0][3], ahK[k][0], bh1 + 2);
            mma_bf16(accH[1][0], ahK[k][1], bh0);  mma_bf16(accH[1][1], ahK[k][1], bh0 + 2);
            mma_bf16(accH[1][2], ahK[k][1], bh1);  mma_bf16(accH[1][3], ahK[k][1], bh1 + 2);
            // corrections: A-hi * B-lo  +  A-lo * B-hi
            mma_bf16(accC[0][0], ahK[k][0], bl0);  mma_bf16(accC[0][1], ahK[k][0], bl0 + 2);
            mma_bf16(accC[0][2], ahK[k][0], bl1);  mma_bf16(accC[0][3], ahK[k][0], bl1 + 2);
            mma_bf16(accC[1][0], ahK[k][1], bl0);  mma_bf16(accC[1][1], ahK[k][1], bl0 + 2);
            mma_bf16(accC[1][2], ahK[k][1], bl1);  mma_bf16(accC[1][3], ahK[k][1], bl1 + 2);
            mma_bf16(accC[0][0], al0, bh0);        mma_bf16(accC[0][1], al0, bh0 + 2);
            mma_bf16(accC[0][2], al0, bh1);        mma_bf16(accC[0][3], al0, bh1 + 2);
            mma_bf16(accC[1][0], al1, bh0);        mma_bf16(accC[1][1], al1, bh0 + 2);
            mma_bf16(accC[1][2], al1, bh1);        mma_bf16(accC[1][3], al1, bh1 + 2);
        }

        // -- Combine and transpose through per-warp staging buffer --
        {
            const int r0 = lane >> 2;
            const int cb = (lane & 3) << 1;
            #pragma unroll
            for (int m = 0; m < 2; ++m)
                #pragma unroll
                for (int n = 0; n < 4; ++n) {
                    const int col = n * 8 + cb;
                    float v0 = accH[m][n][0] + accC[m][n][0];
                    float v1 = accH[m][n][1] + accC[m][n][1];
                    float v2 = accH[m][n][2] + accC[m][n][2];
                    float v3 = accH[m][n][3] + accC[m][n][3];
                    *reinterpret_cast<float2*>(&stage[(m * 16 + r0)     * 34 + col]) = make_float2(v0, v1);
                    *reinterpret_cast<float2*>(&stage[(m * 16 + r0 + 8) * 34 + col]) = make_float2(v2, v3);
                }
        }
        __syncwarp();

        // -- Epilogue: each lane owns one full row of 31 logits --
        {
            const float* biasRow = &sBias[cur * 32];
            const float* lcpRow  = &sLcp[cur * 64];
            float g[NN];
            const float* row = &stage[lane * 34];
            #pragma unroll
            for (int n = 0; n < NN; ++n) {
                float lg = row[n] + biasRow[n];
                g[n] = fmaf(fast_tanh(0.5f * lg), 0.5f, 0.5f);   // sigmoid
            }
            float P[NLF];
            P[0] = 1.0f;
            #pragma unroll
            for (int lvl = 0; lvl < 5; ++lvl) {
                const int base = (1 << lvl) - 1;
                const int cnt  = 1 << lvl;
                #pragma unroll
                for (int j = cnt - 1; j >= 0; --j) {
                    float gg = g[base + j];
                    float pj = P[j];
                    P[2 * j + 1] = pj * gg;
                    P[2 * j]     = fmaf(-pj, gg, pj);
                }
            }
            float t0 = 0.0f, t1 = 0.0f;
            #pragma unroll
            for (int l = 0; l < NLF; ++l) {
                t0 = fmaf(P[l], lcpRow[2 * l],     t0);
                t1 = fmaf(P[l], lcpRow[2 * l + 1], t1);
            }
            o0 += t0; o1 += t1;
        }
        __syncwarp();

        // -- Issue W(t+2) into buf[t&1] + consts(t+2), after all warps done --
        if (t + 2 < NT) {
            __syncthreads();   // all warps finished reading buf[t&1] / consts parity
            const uint8_t* src = reinterpret_cast<const uint8_t*>(&g_W[t + 2][0][0][0]);
            const uint32_t wbn = sbase + SM_W + cur * WBUF_STRIDE;
            #pragma unroll
            for (int j = 0; j < 8; ++j) {
                int idx = tid + j * NTHR;
                int h   = idx >> 9;
                int rem = idx & 511;
                int n   = rem >> 4;
                int k8  = rem & 15;
                cp_async16(wbn + h * WH_STRIDE + n * XSTRB + k8 * 16, src + idx * 16);
            }
            cp_commit();
            if (tid < NN)      sBias[cur * 32 + tid] = sbias[(t + 2) * NN + tid];
            if (tid < NLF * 2) sLcp[cur * 64 + tid]  = g_lcp[(t + 2) * NLF * 2 + tid] * g_tw[t + 2];
        }
    }

    // warp w, lane l owns global row blockIdx*128 + w*32 + l
    const size_t orow = (size_t)blockIdx.x * ROWS + warpM + lane;
    reinterpret_cast<float2*>(out)[orow] = make_float2(o0, o1);
}

// ---------------------------------------------------------------------------
// Launch
// ---------------------------------------------------------------------------
extern "C" void kernel_launch(void* const* d_in, const int* in_sizes, int n_in,
                              void* d_out, int out_size)
{
    const float* x  = (const float*)d_in[0];   // (B, 128)
    const float* sw = (const float*)d_in[1];   // (20, 31, 128)
    const float* sb = (const float*)d_in[2];   // (20, 31)
    const float* ll = (const float*)d_in[3];   // (20, 32, 2)
    const float* tw = (const float*)d_in[4];   // (20,)
    const float* fm = (const float*)d_in[5];   // (20, 128)
    float* out = (float*)d_out;                // (B, 2)

    const int B = in_sizes[0] / NF;

    cudaFuncSetAttribute(forest_mma,
                         cudaFuncAttributeMaxDynamicSharedMemorySize, SM_TOTAL);

    const int prep_total = NT * 32 * NF;
    prep_kernel<<<(prep_total + 255) / 256, 256>>>(sw, ll, tw, fm);
    forest_mma<<<B / ROWS, NTHR, SM_TOTAL>>>(x, sb, out);
}

// round 16
// speedup vs baseline: 2.4158x; 1.6831x over previous
#include <cuda_runtime.h>
#include <cuda_bf16.h>
#include <cstdint>

// ---------------------------------------------------------------------------
// Problem constants
// ---------------------------------------------------------------------------
#define NT   20     // trees
#define NF   128    // features (K)
#define NN   31     // internal nodes (padded to 32 = GEMM N)
#define NLF  32     // leaves
#define ROWS 128    // batch rows per CTA
#define NTHR 128    // 4 warps, m32 per warp
#define XSTRB 272   // x row stride bytes in smem (136 bf16, conflict-free ldmatrix)
#define WSTRB 272   // W row stride bytes in smem
#define WBUF_STRIDE 8704  // bytes per W buffer (32 rows x 272B)

// Shared memory layout (bytes). x-hi tile [0, 34816) lives only during init;
// it is recycled into the W double buffer + stage once A is hoisted to regs.
#define SM_W    0         // 2 x 8704 = 17408
#define SM_STG  17408     // 4 warps x 32 rows x 36 floats = 18432
#define SM_BIAS 35840     // 2 x 32 floats (0.5*bias, double-buffered)
#define SM_LCPW 36096     // 2 x 32 floats (leaf c0 prob * tree weight)
#define SM_TOTAL 36352
#define SM_XHI  0         // init-time x tile (34816 bytes, overlays W+stage)

// ---------------------------------------------------------------------------
// Device scratch (allocation-free)
// ---------------------------------------------------------------------------
__device__ __align__(16) __nv_bfloat16 g_W[NT][32][NF];  // masked weights, bf16
__device__ __align__(16) float g_bias[NT][32];           // 0.5 * split_bias (padded)
__device__ __align__(16) float g_lcpw[NT][32];           // leaf class-0 prob * tree weight

// ---------------------------------------------------------------------------
// Helpers
// ---------------------------------------------------------------------------
__device__ __forceinline__ uint32_t smem_u32(const void* p) {
    uint32_t a;
    asm("{ .reg .u64 t; cvta.to.shared.u64 t, %1; cvt.u32.u64 %0, t; }" : "=r"(a) : "l"(p));
    return a;
}

__device__ __forceinline__ void ldsm4(uint32_t* r, uint32_t addr) {
    asm volatile("ldmatrix.sync.aligned.m8n8.x4.shared.b16 {%0,%1,%2,%3}, [%4];"
                 : "=r"(r[0]), "=r"(r[1]), "=r"(r[2]), "=r"(r[3]) : "r"(addr));
}

__device__ __forceinline__ void mma_bf16(float* c, const uint32_t* a, const uint32_t* b) {
    asm volatile("mma.sync.aligned.m16n8k16.row.col.f32.bf16.bf16.f32 "
                 "{%0,%1,%2,%3}, {%4,%5,%6,%7}, {%8,%9}, {%0,%1,%2,%3};"
                 : "+f"(c[0]), "+f"(c[1]), "+f"(c[2]), "+f"(c[3])
                 : "r"(a[0]), "r"(a[1]), "r"(a[2]), "r"(a[3]), "r"(b[0]), "r"(b[1]));
}

__device__ __forceinline__ void cp_async16(uint32_t smem_dst, const void* gptr) {
    asm volatile("cp.async.cg.shared.global [%0], [%1], 16;"
                 :: "r"(smem_dst), "l"(gptr) : "memory");
}
__device__ __forceinline__ void cp_commit() {
    asm volatile("cp.async.commit_group;" ::: "memory");
}
__device__ __forceinline__ void cp_wait1() {
    asm volatile("cp.async.wait_group 1;" ::: "memory");
}
__device__ __forceinline__ void cp_wait0() {
    asm volatile("cp.async.wait_group 0;" ::: "memory");
}

__device__ __forceinline__ float fast_tanh(float x) {
    float r; asm("tanh.approx.f32 %0, %1;" : "=f"(r) : "f"(x)); return r;
}

__device__ __forceinline__ uint32_t pack_bf2(__nv_bfloat16 a, __nv_bfloat16 b) {
    __nv_bfloat162 t(a, b);
    return *reinterpret_cast<uint32_t*>(&t);
}

// ---------------------------------------------------------------------------
// Prep kernel: bf16 masked weights, half-bias, class0-prob * tree-weight
// ---------------------------------------------------------------------------
__global__ void prep_kernel(const float* __restrict__ sw,
                            const float* __restrict__ sbias,
                            const float* __restrict__ ll,
                            const float* __restrict__ tw,
                            const float* __restrict__ fm)
{
    int idx = blockIdx.x * blockDim.x + threadIdx.x;
    const int total = NT * 32 * NF;
    if (idx < total) {
        int t = idx / (32 * NF);
        int r = (idx / NF) & 31;
        int f = idx & (NF - 1);
        float v = 0.0f;
        if (r < NN) v = sw[(t * NN + r) * NF + f] * fm[t * NF + f];
        g_W[t][r][f] = __float2bfloat16(v);
    }
    if (idx < NT * 32) {
        int t = idx >> 5, n = idx & 31;
        g_bias[t][n] = (n < NN) ? 0.5f * sbias[t * NN + n] : 0.0f;

        // tree softmax (cheap, redundant per thread)
        float m = tw[0];
        #pragma unroll
        for (int q = 1; q < NT; ++q) m = fmaxf(m, tw[q]);
        float s = 0.0f, et = 0.0f;
        #pragma unroll
        for (int q = 0; q < NT; ++q) {
            float e = expf(tw[q] - m);
            s += e;
            if (q == t) et = e;
        }
        float w = et / s;

        // leaf class-0 prob
        float a = ll[(t * NLF + n) * 2], b = ll[(t * NLF + n) * 2 + 1];
        float mm = fmaxf(a, b);
        float e0 = expf(a - mm), e1 = expf(b - mm);
        g_lcpw[t][n] = (e0 / (e0 + e1)) * w;
    }
}

// ---------------------------------------------------------------------------
// Main fused HMMA kernel: pure bf16 GEMM, A in registers, W double-buffered
// via cp.async, 4 warps x m32, 4 CTAs/SM target.
// ---------------------------------------------------------------------------
__global__ __launch_bounds__(NTHR, 4) void forest_mma(
    const float* __restrict__ x,
    float* __restrict__ out)
{
    extern __shared__ __align__(16) uint8_t smem[];
    const uint32_t sbase = smem_u32(smem);

    const int tid  = threadIdx.x;
    const int wid  = tid >> 5;
    const int lane = tid & 31;
    const int grp  = lane >> 3;
    const int sub  = lane & 7;

    float* stage = reinterpret_cast<float*>(smem + SM_STG) + wid * 32 * 36;
    float* sBias = reinterpret_cast<float*>(smem + SM_BIAS);   // [2][32]
    float* sLcpw = reinterpret_cast<float*>(smem + SM_LCPW);   // [2][32]

    // ---- Init: load x tile as bf16 into XHI (temporary) ----
    {
        const float4* x4 = reinterpret_cast<const float4*>(
            x + (size_t)blockIdx.x * ROWS * NF);
        #pragma unroll
        for (int i = 0; i < 32; ++i) {            // 4096 float4 / 128 threads
            int lin = tid + i * NTHR;
            int r  = lin >> 5;
            int c4 = lin & 31;
            float4 v = x4[lin];
            uint32_t* dh = reinterpret_cast<uint32_t*>(smem + SM_XHI + r * XSTRB + c4 * 8);
            dh[0] = pack_bf2(__float2bfloat16(v.x), __float2bfloat16(v.y));
            dh[1] = pack_bf2(__float2bfloat16(v.z), __float2bfloat16(v.w));
        }
    }
    __syncthreads();

    // ---- Hoist A fragments into persistent registers (64 regs) ----
    const int aRow  = ((grp & 1) << 3) + sub;
    const int aCol  = (grp >> 1) << 4;            // bytes
    const int warpM = wid << 5;                   // 32 rows per warp
    const uint32_t aHi = sbase + SM_XHI + (warpM + aRow) * XSTRB + aCol;
    uint32_t ahK[8][2][4];
    #pragma unroll
    for (int k = 0; k < 8; ++k) {
        ldsm4(ahK[k][0], aHi + k * 32);
        ldsm4(ahK[k][1], aHi + 16 * XSTRB + k * 32);
    }
    __syncthreads();   // all warps done reading XHI; safe to overwrite via cp.async

    // ---- Issue W(0), W(1) + consts via cp.async (one commit group per tree) ----
    #pragma unroll
    for (int b = 0; b < 2; ++b) {
        const uint8_t* src = reinterpret_cast<const uint8_t*>(&g_W[b][0][0]);
        const uint32_t wb  = sbase + SM_W + b * WBUF_STRIDE;
        #pragma unroll
        for (int j = 0; j < 4; ++j) {             // 512 x 16B chunks
            int idx = tid + j * NTHR;
            int n   = idx >> 4;
            int c   = idx & 15;
            cp_async16(wb + n * WSTRB + c * 16, src + idx * 16);
        }
        if (tid < 8)
            cp_async16(sbase + SM_BIAS + b * 128 + tid * 16,
                       reinterpret_cast<const uint8_t*>(&g_bias[b][0]) + tid * 16);
        else if (tid < 16)
            cp_async16(sbase + SM_LCPW + b * 128 + (tid - 8) * 16,
                       reinterpret_cast<const uint8_t*>(&g_lcpw[b][0]) + (tid - 8) * 16);
        cp_commit();
    }

    // ---- B-operand ldmatrix addressing ----
    const int bRow = ((grp >> 1) << 3) + sub;
    const int bCol = (grp & 1) << 4;              // bytes

    float o0 = 0.0f;

    for (int t = 0; t < NT; ++t) {
        const int cur = t & 1;
        if (t == NT - 1) cp_wait0(); else cp_wait1();   // W(t) landed
        __syncthreads();

        const uint32_t wb  = sbase + SM_W + cur * WBUF_STRIDE;
        const uint32_t bHi0 = wb + bRow * WSTRB + bCol;   // n-tiles 0,1
        const uint32_t bHi1 = bHi0 + 16 * WSTRB;          // n-tiles 2,3

        // -- K loop: 2 ldsm4 + 8 MMA per k-step --
        float acc[2][4][4];
        #pragma unroll
        for (int m = 0; m < 2; ++m)
            #pragma unroll
            for (int n = 0; n < 4; ++n)
                #pragma unroll
                for (int i = 0; i < 4; ++i) acc[m][n][i] = 0.0f;

        #pragma unroll
        for (int k = 0; k < 8; ++k) {
            const uint32_t ko = k * 32;
            uint32_t bh0[4], bh1[4];
            ldsm4(bh0, bHi0 + ko);
            ldsm4(bh1, bHi1 + ko);
            mma_bf16(acc[0][0], ahK[k][0], bh0);  mma_bf16(acc[0][1], ahK[k][0], bh0 + 2);
            mma_bf16(acc[0][2], ahK[k][0], bh1);  mma_bf16(acc[0][3], ahK[k][0], bh1 + 2);
            mma_bf16(acc[1][0], ahK[k][1], bh0);  mma_bf16(acc[1][1], ahK[k][1], bh0 + 2);
            mma_bf16(acc[1][2], ahK[k][1], bh1);  mma_bf16(acc[1][3], ahK[k][1], bh1 + 2);
        }

        // -- Transpose through per-warp staging buffer (stride 36 floats) --
        {
            const int r0 = lane >> 2;
            const int cb = (lane & 3) << 1;
            #pragma unroll
            for (int m = 0; m < 2; ++m)
                #pragma unroll
                for (int n = 0; n < 4; ++n) {
                    const int col = n * 8 + cb;
                    *reinterpret_cast<float2*>(&stage[(m * 16 + r0)     * 36 + col]) =
                        make_float2(acc[m][n][0], acc[m][n][1]);
                    *reinterpret_cast<float2*>(&stage[(m * 16 + r0 + 8) * 36 + col]) =
                        make_float2(acc[m][n][2], acc[m][n][3]);
                }
        }
        __syncwarp();

        // -- Epilogue: each lane owns one full row of 31 logits --
        {
            const float* biasRow = &sBias[cur * 32];
            const float* lcpRow  = &sLcpw[cur * 32];
            float g[32];
            const float4* rowv = reinterpret_cast<const float4*>(&stage[lane * 36]);
            #pragma unroll
            for (int i = 0; i < 8; ++i) {
                float4 v = rowv[i];
                // sigmoid(l + b) = 0.5 + 0.5*tanh(0.5*l + 0.5*b); biasRow holds 0.5*b
                g[4*i+0] = fmaf(fast_tanh(fmaf(0.5f, v.x, biasRow[4*i+0])), 0.5f, 0.5f);
                g[4*i+1] = fmaf(fast_tanh(fmaf(0.5f, v.y, biasRow[4*i+1])), 0.5f, 0.5f);
                g[4*i+2] = fmaf(fast_tanh(fmaf(0.5f, v.z, biasRow[4*i+2])), 0.5f, 0.5f);
                g[4*i+3] = fmaf(fast_tanh(fmaf(0.5f, v.w, biasRow[4*i+3])), 0.5f, 0.5f);
            }
            float P[NLF];
            P[0] = 1.0f;
            #pragma unroll
            for (int lvl = 0; lvl < 5; ++lvl) {
                const int base = (1 << lvl) - 1;
                const int cnt  = 1 << lvl;
                #pragma unroll
                for (int j = cnt - 1; j >= 0; --j) {
                    float gg = g[base + j];
                    float pj = P[j];
                    P[2 * j + 1] = pj * gg;
                    P[2 * j]     = fmaf(-pj, gg, pj);
                }
            }
            float t0 = 0.0f;
            #pragma unroll
            for (int l = 0; l < NLF; ++l)
                t0 = fmaf(P[l], lcpRow[l], t0);
            o0 += t0;
        }
        __syncwarp();

        // -- Issue W(t+2) + consts(t+2) into parity buffer cur --
        if (t + 2 < NT) {
            __syncthreads();   // all warps finished reading buffer cur
            const uint8_t* src = reinterpret_cast<const uint8_t*>(&g_W[t + 2][0][0]);
            const uint32_t wbn = sbase + SM_W + cur * WBUF_STRIDE;
            #pragma unroll
            for (int j = 0; j < 4; ++j) {
                int idx = tid + j * NTHR;
                int n   = idx >> 4;
                int c   = idx & 15;
                cp_async16(wbn + n * WSTRB + c * 16, src + idx * 16);
            }
            if (tid < 8)
                cp_async16(sbase + SM_BIAS + cur * 128 + tid * 16,
                           reinterpret_cast<const uint8_t*>(&g_bias[t + 2][0]) + tid * 16);
            else if (tid < 16)
                cp_async16(sbase + SM_LCPW + cur * 128 + (tid - 8) * 16,
                           reinterpret_cast<const uint8_t*>(&g_lcpw[t + 2][0]) + (tid - 8) * 16);
            cp_commit();
        }
    }

    // warp w, lane l owns global row blockIdx*128 + w*32 + l.
    // Two-class softmax + softmax tree weights => o1 = 1 - o0 exactly.
    const size_t orow = (size_t)blockIdx.x * ROWS + warpM + lane;
    reinterpret_cast<float2*>(out)[orow] = make_float2(o0, 1.0f - o0);
}

// ---------------------------------------------------------------------------
// Launch
// ---------------------------------------------------------------------------
extern "C" void kernel_launch(void* const* d_in, const int* in_sizes, int n_in,
                              void* d_out, int out_size)
{
    const float* x  = (const float*)d_in[0];   // (B, 128)
    const float* sw = (const float*)d_in[1];   // (20, 31, 128)
    const float* sb = (const float*)d_in[2];   // (20, 31)
    const float* ll = (const float*)d_in[3];   // (20, 32, 2)
    const float* tw = (const float*)d_in[4];   // (20,)
    const float* fm = (const float*)d_in[5];   // (20, 128)
    float* out = (float*)d_out;                // (B, 2)

    const int B = in_sizes[0] / NF;

    cudaFuncSetAttribute(forest_mma,
                         cudaFuncAttributeMaxDynamicSharedMemorySize, SM_TOTAL);

    const int prep_total = NT * 32 * NF;
    prep_kernel<<<(prep_total + 255) / 256, 256>>>(sw, sb, ll, tw, fm);
    forest_mma<<<B / ROWS, NTHR, SM_TOTAL>>>(x, out);
}